// round 11
// baseline (speedup 1.0000x reference)
#include <cuda_runtime.h>
#include <cuda_fp16.h>
#include <cuda_bf16.h>
#include <cstdint>

#define NB_   32
#define TENC_ 500
#define D_    1024
#define DM_   1024
#define TDEC_ 100
#define E_    256
#define C_    8000
#define G3_   (3*DM_)   // 3072

#define GROUPS 4
#define NPG    8        // batch elements per group
#define BPG    74       // blocks per group (4*74 = 296 = 148 SMs x 2)

// ---------------- scratch (device globals; no allocations allowed) ----------
__device__ __half g_keysh[NB_*TENC_*DM_];    // 32.8 MB fp16
__device__ __half g_xh[NB_*TENC_*D_];        // 32.8 MB fp16 copy of x
__device__ __half g_W2t[DM_*DM_];            // W2^T fp16 [j][k]
__device__ __half g_Wxt[G3_*DM_];            // Wx^T (context rows) fp16 [j][k]
__device__ float g_yemb[NB_*TDEC_*E_];
__device__ float g_gxemb[NB_*TDEC_*G3_];     // 39.3 MB (includes b_in)
__device__ float g_q[NB_*DM_];               // q (with b2 added)
__device__ float g_scores[NB_*TENC_];
__device__ float g_ctxpart[2*NB_*D_];        // 2 t-half partials
__device__ float g_gx[NB_*G3_];              // ctx @ Wx
__device__ float g_H[NB_*TDEC_*DM_];         // 13.1 MB
// group barriers
__device__ unsigned g_cnt[GROUPS];
__device__ volatile unsigned g_gen[GROUPS];
// split-bf16 staging for tensor-core GEMMs
__device__ __nv_bfloat16 g_Ah[16000*1024];
__device__ __nv_bfloat16 g_Al[16000*1024];
__device__ __nv_bfloat16 g_Bh[1024*8000];
__device__ __nv_bfloat16 g_Bl[1024*8000];

__device__ __forceinline__ float tanh_approx(float x) {
    float y;
    asm("tanh.approx.f32 %0, %1;" : "=f"(y) : "f"(x));
    return y;
}

// ---------------- tensor-core / async-copy primitives ------------------------
__device__ __forceinline__ void ldsm4(uint32_t* r, uint32_t addr) {
    asm volatile("ldmatrix.sync.aligned.m8n8.x4.shared.b16 {%0,%1,%2,%3}, [%4];"
        : "=r"(r[0]), "=r"(r[1]), "=r"(r[2]), "=r"(r[3]) : "r"(addr));
}
__device__ __forceinline__ void ldsm4t(uint32_t* r, uint32_t addr) {
    asm volatile("ldmatrix.sync.aligned.m8n8.x4.trans.shared.b16 {%0,%1,%2,%3}, [%4];"
        : "=r"(r[0]), "=r"(r[1]), "=r"(r[2]), "=r"(r[3]) : "r"(addr));
}
__device__ __forceinline__ void mma16816(float* c, const uint32_t* a, const uint32_t* b) {
    asm volatile("mma.sync.aligned.m16n8k16.row.col.f32.bf16.bf16.f32 "
        "{%0,%1,%2,%3},{%4,%5,%6,%7},{%8,%9},{%0,%1,%2,%3};"
        : "+f"(c[0]), "+f"(c[1]), "+f"(c[2]), "+f"(c[3])
        : "r"(a[0]), "r"(a[1]), "r"(a[2]), "r"(a[3]), "r"(b[0]), "r"(b[1]));
}
__device__ __forceinline__ void cpa16(uint32_t dst, const void* src) {
    asm volatile("cp.async.cg.shared.global [%0], [%1], 16;" :: "r"(dst), "l"(src));
}
__device__ __forceinline__ void cpa16z(uint32_t dst, const void* src, bool ok) {
    int sz = ok ? 16 : 0;
    asm volatile("cp.async.cg.shared.global [%0], [%1], 16, %2;"
                 :: "r"(dst), "l"(src), "r"(sz));
}

// ---------------- split fp32 -> (bf16 hi, bf16 lo) ---------------------------
__global__ void split_bf16(const float* __restrict__ src,
                           __nv_bfloat16* __restrict__ hi,
                           __nv_bfloat16* __restrict__ lo, int n4)
{
    int i = blockIdx.x * blockDim.x + threadIdx.x;
    if (i < n4) {
        float4 v = ((const float4*)src)[i];
        __nv_bfloat16 h0 = __float2bfloat16(v.x);
        __nv_bfloat16 h1 = __float2bfloat16(v.y);
        __nv_bfloat16 h2 = __float2bfloat16(v.z);
        __nv_bfloat16 h3 = __float2bfloat16(v.w);
        __nv_bfloat162 hh0; hh0.x = h0; hh0.y = h1;
        __nv_bfloat162 hh1; hh1.x = h2; hh1.y = h3;
        ((__nv_bfloat162*)hi)[2*i]   = hh0;
        ((__nv_bfloat162*)hi)[2*i+1] = hh1;
        __nv_bfloat162 ll0, ll1;
        ll0.x = __float2bfloat16(v.x - __bfloat162float(h0));
        ll0.y = __float2bfloat16(v.y - __bfloat162float(h1));
        ll1.x = __float2bfloat16(v.z - __bfloat162float(h2));
        ll1.y = __float2bfloat16(v.w - __bfloat162float(h3));
        ((__nv_bfloat162*)lo)[2*i]   = ll0;
        ((__nv_bfloat162*)lo)[2*i+1] = ll1;
    }
}

// ---------------- split-bf16 tensor-core GEMM, cp.async double-buffered ------
#define HG_BUF_ELEMS 18944
#define HG_SMEM_BYTES (2 * HG_BUF_ELEMS * 2)
template <typename OutT>
__global__ __launch_bounds__(256, 2) void hgemm_split(
    const __nv_bfloat16* __restrict__ Ah, const __nv_bfloat16* __restrict__ Al,
    const __nv_bfloat16* __restrict__ Bh, const __nv_bfloat16* __restrict__ Bl,
    const float* __restrict__ bias, OutT* __restrict__ C,
    int M, int N, int K)
{
    extern __shared__ __nv_bfloat16 smem_hg[];
    const uint32_t sbase = (uint32_t)__cvta_generic_to_shared(smem_hg);

    const int m0 = blockIdx.x * 128;
    const int n0 = blockIdx.y * 128;
    const int tid = threadIdx.x;
    const int wid = tid >> 5, lane = tid & 31;
    const int wm = wid >> 2, wn = wid & 3;

    float acc[4][4][4] = {};

    const int arow = tid >> 2;
    const int acol = (tid & 3) * 8;
    const int bk   = tid >> 4;
    const int bcol = (tid & 15) * 8;
    const bool bok = (n0 + bcol) < N;

    const int nk = K >> 5;

    auto loadTile = [&](int buf, int k0) {
        const uint32_t b0 = sbase + (uint32_t)buf * (HG_BUF_ELEMS * 2);
        cpa16(b0 + (uint32_t)((arow*40 + acol) * 2),
              Ah + (size_t)(m0 + arow) * K + k0 + acol);
        cpa16(b0 + (uint32_t)(((arow+64)*40 + acol) * 2),
              Ah + (size_t)(m0 + arow + 64) * K + k0 + acol);
        const uint32_t l0 = b0 + 5120*2;
        cpa16(l0 + (uint32_t)((arow*40 + acol) * 2),
              Al + (size_t)(m0 + arow) * K + k0 + acol);
        cpa16(l0 + (uint32_t)(((arow+64)*40 + acol) * 2),
              Al + (size_t)(m0 + arow + 64) * K + k0 + acol);
        const uint32_t bh0 = b0 + 10240*2;
        cpa16z(bh0 + (uint32_t)((bk*136 + bcol) * 2),
               Bh + (size_t)(k0 + bk) * N + n0 + bcol, bok);
        cpa16z(bh0 + (uint32_t)(((bk+16)*136 + bcol) * 2),
               Bh + (size_t)(k0 + bk + 16) * N + n0 + bcol, bok);
        const uint32_t bl0 = b0 + 14592*2;
        cpa16z(bl0 + (uint32_t)((bk*136 + bcol) * 2),
               Bl + (size_t)(k0 + bk) * N + n0 + bcol, bok);
        cpa16z(bl0 + (uint32_t)(((bk+16)*136 + bcol) * 2),
               Bl + (size_t)(k0 + bk + 16) * N + n0 + bcol, bok);
        asm volatile("cp.async.commit_group;");
    };

    loadTile(0, 0);

    for (int kt = 0; kt < nk; kt++) {
        const int buf = kt & 1;
        if (kt + 1 < nk) {
            loadTile(buf ^ 1, (kt + 1) << 5);
            asm volatile("cp.async.wait_group 1;");
        } else {
            asm volatile("cp.async.wait_group 0;");
        }
        __syncthreads();

        const uint32_t bb = sbase + (uint32_t)buf * (HG_BUF_ELEMS * 2);
        const uint32_t as_h = bb;
        const uint32_t as_l = bb + 10240;
        const uint32_t bs_h = bb + 20480;
        const uint32_t bs_l = bb + 29184;

#pragma unroll
        for (int kk = 0; kk < 32; kk += 16) {
            uint32_t ah[4][4], al[4][4], bh[4][2], bl[4][2];
#pragma unroll
            for (int mt = 0; mt < 4; mt++) {
                const uint32_t off =
                    (uint32_t)(((wm*64 + mt*16 + (lane & 15)) * 40
                                + kk + ((lane >> 4) << 3)) << 1);
                ldsm4(ah[mt], as_h + off);
                ldsm4(al[mt], as_l + off);
            }
#pragma unroll
            for (int ng = 0; ng < 2; ng++) {
                const uint32_t off =
                    (uint32_t)((((kk + (lane & 15)) * 136)
                                + wn*32 + ng*16 + ((lane >> 4) << 3)) << 1);
                uint32_t r[4];
                ldsm4t(r, bs_h + off);
                bh[2*ng][0] = r[0]; bh[2*ng][1] = r[1];
                bh[2*ng+1][0] = r[2]; bh[2*ng+1][1] = r[3];
                ldsm4t(r, bs_l + off);
                bl[2*ng][0] = r[0]; bl[2*ng][1] = r[1];
                bl[2*ng+1][0] = r[2]; bl[2*ng+1][1] = r[3];
            }
#pragma unroll
            for (int mt = 0; mt < 4; mt++)
#pragma unroll
                for (int nt = 0; nt < 4; nt++) {
                    mma16816(acc[mt][nt], ah[mt], bh[nt]);
                    mma16816(acc[mt][nt], ah[mt], bl[nt]);
                    mma16816(acc[mt][nt], al[mt], bh[nt]);
                }
        }
        __syncthreads();
    }

    const int tr = lane >> 2;
    const int tc = (lane & 3) * 2;
#pragma unroll
    for (int mt = 0; mt < 4; mt++) {
#pragma unroll
        for (int nt = 0; nt < 4; nt++) {
            const int col = n0 + wn*32 + nt*8 + tc;
            if (col < N) {
                const float b0 = bias[col], b1 = bias[col+1];
                const int r0 = m0 + wm*64 + mt*16 + tr;
                OutT* p0 = C + (size_t)r0 * N + col;
                OutT* p1 = C + (size_t)(r0 + 8) * N + col;
                p0[0] = (OutT)(acc[mt][nt][0] + b0);
                p0[1] = (OutT)(acc[mt][nt][1] + b1);
                p1[0] = (OutT)(acc[mt][nt][2] + b0);
                p1[1] = (OutT)(acc[mt][nt][3] + b1);
            }
        }
    }
}

// ---------------- transpose fp32 -> fp16 -------------------------------------
__global__ void transpose_f16(const float* __restrict__ src,
                              __half* __restrict__ dst,
                              int R, int ldsrc)
{
    __shared__ float tile[32][33];
    const int r0 = blockIdx.y * 32, c0 = blockIdx.x * 32;
    for (int i = threadIdx.y; i < 32; i += 8)
        tile[i][threadIdx.x] = src[(size_t)(r0 + i) * ldsrc + c0 + threadIdx.x];
    __syncthreads();
    for (int i = threadIdx.y; i < 32; i += 8)
        dst[(size_t)(c0 + i) * R + r0 + threadIdx.x] =
            __float2half(tile[threadIdx.x][i]);
}

// ---------------- fp32 -> fp16 bulk convert ---------------------------------
__global__ void f32_to_f16(const float* __restrict__ src,
                           __half* __restrict__ dst, int n4)
{
    int i = blockIdx.x * blockDim.x + threadIdx.x;
    if (i < n4) {
        float4 v = ((const float4*)src)[i];
        ((__half2*)dst)[2*i]   = __floats2half2_rn(v.x, v.y);
        ((__half2*)dst)[2*i+1] = __floats2half2_rn(v.z, v.w);
    }
}

// ---------------- embedding gather ------------------------------------------
__global__ void gather_emb(const int* __restrict__ y, const float* __restrict__ emb,
                           float* __restrict__ out)
{
    int idx = blockIdx.x * blockDim.x + threadIdx.x;
    if (idx < NB_*TDEC_*E_) {
        int row = idx >> 8;
        int e   = idx & 255;
        out[idx] = emb[(size_t)y[row] * E_ + e];
    }
}

// ---------------- persistent grouped decode loop ------------------------------
// 296 blocks = 4 groups x 74. Each group owns 8 batch elements, syncs only
// within itself. 4 group-barriers per step.
__global__ __launch_bounds__(256, 2) void decode_loop(
    const float* __restrict__ m, const float* __restrict__ v,
    const float* __restrict__ bv, const float* __restrict__ b_rec)
{
    __shared__ float sh[10304];   // 8 rows x 1032 (8256) + 2048 reduce = 40.2 KB

    const int g   = blockIdx.x / BPG;
    const int r   = blockIdx.x % BPG;
    const int tid = threadIdx.x;
    const int w = tid >> 5, lane = tid & 31;
    const int tx = tid & 31, ty = tid >> 5;
    const float bvv = bv[0];

    auto group_sync = [&]() {
        __syncthreads();
        __threadfence();
        if (tid == 0) {
            unsigned gen = g_gen[g];
            if (atomicAdd(&g_cnt[g], 1u) == BPG - 1u) {
                g_cnt[g] = 0u;
                __threadfence();
                g_gen[g] = gen + 1u;
            } else {
                while (g_gen[g] == gen) __nanosleep(32);
                __threadfence();
            }
        }
        __syncthreads();
    };

    for (int t = 0; t <= TDEC_; t++) {
        // ===== Phase A: gate(gx_{t-1}) -> h (smem), write H[t-1], q_t =====
        if (r < 32) {
            if (t == 0) {
#pragma unroll 4
                for (int i = 0; i < 32; i++) {
                    int idx = tid + i*256;
                    int nl = idx >> 10, k = idx & 1023;
                    sh[nl*1032 + k] = m[(size_t)(g*NPG + nl)*1024 + k];
                }
            } else {
#pragma unroll 2
                for (int i = 0; i < 32; i++) {
                    int idx = tid + i*256;
                    int nl = idx >> 10, k = idx & 1023;
                    int n = g*NPG + nl;
                    const float* gx = g_gx + (size_t)n*G3_;
                    const float* ge = g_gxemb + ((size_t)n*TDEC_ + (t-1))*G3_;
                    float xz = gx[k]        + ge[k];
                    float xr = gx[k+1024]   + ge[k+1024];
                    float xhh= gx[k+2048]   + ge[k+2048];
                    float z  = 1.f/(1.f+__expf(-(xz + b_rec[k])));
                    float rr = 1.f/(1.f+__expf(-(xr + b_rec[k+1024])));
                    float hh = tanhf(xhh + rr*b_rec[k+2048]);
                    float hv = (1.f - z)*hh;
                    sh[nl*1032 + k] = hv;
                    if (r == 0)
                        g_H[((size_t)n*TDEC_ + (t-1))*DM_ + k] = hv;
                }
            }
            __syncthreads();
            if (t < TDEC_) {
                // q[j] for j in [r*32, r*32+32), all 8 n; k split over ty
                const int j = r*32 + tx;
                const uint4* wp = (const uint4*)(g_W2t + (size_t)j*1024);
                float acc[8] = {};
                for (int kk = ty*128; kk < ty*128 + 128; kk += 8) {
                    uint4 u = wp[kk >> 3];
                    const __half2* hp = (const __half2*)&u;
                    float wv[8];
                    float2 f0=__half22float2(hp[0]); wv[0]=f0.x; wv[1]=f0.y;
                    float2 f1=__half22float2(hp[1]); wv[2]=f1.x; wv[3]=f1.y;
                    float2 f2=__half22float2(hp[2]); wv[4]=f2.x; wv[5]=f2.y;
                    float2 f3=__half22float2(hp[3]); wv[6]=f3.x; wv[7]=f3.y;
#pragma unroll
                    for (int nl = 0; nl < 8; nl++) {
                        float4 c0 = *(const float4*)&sh[nl*1032 + kk];
                        float4 c1 = *(const float4*)&sh[nl*1032 + kk + 4];
                        acc[nl] = fmaf(wv[0], c0.x, acc[nl]);
                        acc[nl] = fmaf(wv[1], c0.y, acc[nl]);
                        acc[nl] = fmaf(wv[2], c0.z, acc[nl]);
                        acc[nl] = fmaf(wv[3], c0.w, acc[nl]);
                        acc[nl] = fmaf(wv[4], c1.x, acc[nl]);
                        acc[nl] = fmaf(wv[5], c1.y, acc[nl]);
                        acc[nl] = fmaf(wv[6], c1.z, acc[nl]);
                        acc[nl] = fmaf(wv[7], c1.w, acc[nl]);
                    }
                }
                float* rsh = sh + 8256;
#pragma unroll
                for (int nl = 0; nl < 8; nl++)
                    rsh[ty*256 + tx*8 + nl] = acc[nl];
                __syncthreads();
                {
                    // tid encodes (j-lane = tid>>3, n = tid&7)
                    float s = 0.f;
#pragma unroll
                    for (int c = 0; c < 8; c++) s += rsh[c*256 + tid];
                    int jf = tid >> 3, nf = tid & 7;
                    g_q[(size_t)(g*NPG + nf)*1024 + r*32 + jf] = s;  // b2 added in B
                }
            }
        }
        if (t == TDEC_) break;   // all blocks exit together (no barrier needed)
        group_sync();

        // ===== Phase B: score (all 74 blocks; t-slice x 8 n tasks) =====
        {
#pragma unroll 4
            for (int i = 0; i < 32; i++) {
                int idx = tid + i*256;
                int nl = idx >> 10, d = idx & 1023;
                sh[nl*1032 + d] = g_q[(size_t)(g*NPG + nl)*1024 + d];
            }
            for (int d = tid; d < 1024; d += 256) sh[8256 + d] = v[d];
            __syncthreads();

            const int t0 = (TENC_ * r) / BPG;
            const int t1 = (TENC_ * (r + 1)) / BPG;
            const int ntask = (t1 - t0) * NPG;
            const float* vs = sh + 8256;
            for (int task = w; task < ntask; task += 8) {
                const int nl = task & 7;
                const int tt = t0 + (task >> 3);
                const int n = g*NPG + nl;
                const uint4* kp = (const uint4*)(g_keysh + ((size_t)(n*TENC_ + tt) << 10));
                const float* qs = sh + nl*1032;
                float acc = 0.f;
#pragma unroll
                for (int i = 0; i < 4; i++) {
                    uint4 u = kp[lane + (i << 5)];
                    const __half2* hp = (const __half2*)&u;
                    const int d0 = (lane + (i << 5)) << 3;
                    float4 q1 = *(const float4*)&qs[d0];
                    float4 q2 = *(const float4*)&qs[d0 + 4];
                    float4 v1 = *(const float4*)&vs[d0];
                    float4 v2 = *(const float4*)&vs[d0 + 4];
                    float2 f0 = __half22float2(hp[0]);
                    float2 f1 = __half22float2(hp[1]);
                    float2 f2 = __half22float2(hp[2]);
                    float2 f3 = __half22float2(hp[3]);
                    acc = fmaf(tanh_approx(f0.x + q1.x), v1.x, acc);
                    acc = fmaf(tanh_approx(f0.y + q1.y), v1.y, acc);
                    acc = fmaf(tanh_approx(f1.x + q1.z), v1.z, acc);
                    acc = fmaf(tanh_approx(f1.y + q1.w), v1.w, acc);
                    acc = fmaf(tanh_approx(f2.x + q2.x), v2.x, acc);
                    acc = fmaf(tanh_approx(f2.y + q2.y), v2.y, acc);
                    acc = fmaf(tanh_approx(f3.x + q2.z), v2.z, acc);
                    acc = fmaf(tanh_approx(f3.y + q2.w), v2.w, acc);
                }
#pragma unroll
                for (int off = 16; off; off >>= 1)
                    acc += __shfl_xor_sync(0xffffffffu, acc, off);
                if (lane == 0) g_scores[n*TENC_ + tt] = acc + bvv;
            }
        }
        group_sync();

        // ===== Phase C: softmax (redundant per block) + context partials =====
        if (r < 64) {
            const int nl = r >> 3;
            const int tc = (r >> 2) & 1;
            const int dc = r & 3;
            const int n = g*NPG + nl;
            float* ws  = sh;
            float* red = sh + 512;

            float mx = -1e30f;
            for (int s_ = tid; s_ < TENC_; s_ += 256) {
                float sc = g_scores[n*TENC_ + s_];
                ws[s_] = sc;
                mx = fmaxf(mx, sc);
            }
            red[tid] = mx; __syncthreads();
            for (int s_ = 128; s_; s_ >>= 1) {
                if (tid < s_) red[tid] = fmaxf(red[tid], red[tid+s_]);
                __syncthreads();
            }
            mx = red[0];
            __syncthreads();
            float lsum = 0.f;
            for (int s_ = tid; s_ < TENC_; s_ += 256) {
                float e = __expf(ws[s_] - mx);
                ws[s_] = e;
                lsum += e;
            }
            red[tid] = lsum; __syncthreads();
            for (int s_ = 128; s_; s_ >>= 1) {
                if (tid < s_) red[tid] += red[tid+s_];
                __syncthreads();
            }
            const float inv = 1.f / red[0];

            const __half* xp = g_xh + (size_t)n * TENC_ * D_ + dc*256 + tid;
            const int tt0 = tc * 250;
            float a[5];
#pragma unroll
            for (int u = 0; u < 5; u++) a[u] = 0.f;
            for (int tt = tt0; tt < tt0 + 250; tt += 5) {
#pragma unroll
                for (int u = 0; u < 5; u++)
                    a[u] = fmaf(ws[tt+u], __half2float(xp[(size_t)(tt+u) << 10]), a[u]);
            }
            g_ctxpart[((size_t)tc * NB_ + n) * 1024 + dc*256 + tid] =
                (((a[0]+a[1]) + (a[2]+a[3])) + a[4]) * inv;
        }
        group_sync();

        // ===== Phase D: gx = ctx @ Wxt (full K, in-block k-split reduce) =====
        if (r < 64) {
#pragma unroll 4
            for (int i = 0; i < 32; i++) {
                int idx = tid + i*256;
                int nl = idx >> 10, k = idx & 1023;
                int n = g*NPG + nl;
                sh[nl*1032 + k] = g_ctxpart[(size_t)n*1024 + k]
                                + g_ctxpart[(size_t)(NB_ + n)*1024 + k];
            }
            __syncthreads();

            for (int jj = r; jj < 96; jj += 64) {
                const int j = jj*32 + tx;
                const uint4* wp = (const uint4*)(g_Wxt + (size_t)j*1024);
                float acc[8] = {};
                for (int kk = ty*128; kk < ty*128 + 128; kk += 8) {
                    uint4 u = wp[kk >> 3];
                    const __half2* hp = (const __half2*)&u;
                    float wv[8];
                    float2 f0=__half22float2(hp[0]); wv[0]=f0.x; wv[1]=f0.y;
                    float2 f1=__half22float2(hp[1]); wv[2]=f1.x; wv[3]=f1.y;
                    float2 f2=__half22float2(hp[2]); wv[4]=f2.x; wv[5]=f2.y;
                    float2 f3=__half22float2(hp[3]); wv[6]=f3.x; wv[7]=f3.y;
#pragma unroll
                    for (int nl = 0; nl < 8; nl++) {
                        float4 c0 = *(const float4*)&sh[nl*1032 + kk];
                        float4 c1 = *(const float4*)&sh[nl*1032 + kk + 4];
                        acc[nl] = fmaf(wv[0], c0.x, acc[nl]);
                        acc[nl] = fmaf(wv[1], c0.y, acc[nl]);
                        acc[nl] = fmaf(wv[2], c0.z, acc[nl]);
                        acc[nl] = fmaf(wv[3], c0.w, acc[nl]);
                        acc[nl] = fmaf(wv[4], c1.x, acc[nl]);
                        acc[nl] = fmaf(wv[5], c1.y, acc[nl]);
                        acc[nl] = fmaf(wv[6], c1.z, acc[nl]);
                        acc[nl] = fmaf(wv[7], c1.w, acc[nl]);
                    }
                }
                float* rsh = sh + 8256;
#pragma unroll
                for (int nl = 0; nl < 8; nl++)
                    rsh[ty*256 + tx*8 + nl] = acc[nl];
                __syncthreads();
                {
                    float s = 0.f;
#pragma unroll
                    for (int c = 0; c < 8; c++) s += rsh[c*256 + tid];
                    int jf = tid >> 3, nf = tid & 7;
                    g_gx[(size_t)(g*NPG + nf)*G3_ + jj*32 + jf] = s;
                }
                __syncthreads();
            }
        }
        group_sync();
    }
}

// ---------------- launch -----------------------------------------------------
extern "C" void kernel_launch(void* const* d_in, const int* in_sizes, int n_in,
                              void* d_out, int out_size)
{
    (void)in_sizes; (void)n_in; (void)out_size;
    const float* x    = (const float*)d_in[0];
    const float* m    = (const float*)d_in[1];
    const int*   y    = (const int*)  d_in[2];
    const float* emb  = (const float*)d_in[3];
    const float* W1   = (const float*)d_in[4];
    const float* b1   = (const float*)d_in[5];
    const float* W2   = (const float*)d_in[6];
    const float* b2   = (const float*)d_in[7];
    const float* v    = (const float*)d_in[8];
    const float* bv   = (const float*)d_in[9];
    const float* Wx   = (const float*)d_in[10];
    // d_in[11] = Uh — provably unused (h_prev == 0)
    const float* b_in = (const float*)d_in[12];
    const float* b_rec= (const float*)d_in[13];
    const float* Wo   = (const float*)d_in[14];
    const float* bo   = (const float*)d_in[15];
    float* out = (float*)d_out;

    __half *keysh, *xh, *W2t, *Wxt;
    __nv_bfloat16 *Ah, *Al, *Bh, *Bl;
    float *yemb, *gxemb, *H;
    cudaGetSymbolAddress((void**)&keysh,  g_keysh);
    cudaGetSymbolAddress((void**)&xh,     g_xh);
    cudaGetSymbolAddress((void**)&W2t,    g_W2t);
    cudaGetSymbolAddress((void**)&Wxt,    g_Wxt);
    cudaGetSymbolAddress((void**)&yemb,   g_yemb);
    cudaGetSymbolAddress((void**)&gxemb,  g_gxemb);
    cudaGetSymbolAddress((void**)&H,      g_H);
    cudaGetSymbolAddress((void**)&Ah,     g_Ah);
    cudaGetSymbolAddress((void**)&Al,     g_Al);
    cudaGetSymbolAddress((void**)&Bh,     g_Bh);
    cudaGetSymbolAddress((void**)&Bl,     g_Bl);

    cudaFuncSetAttribute(hgemm_split<__half>,
        cudaFuncAttributeMaxDynamicSharedMemorySize, HG_SMEM_BYTES);
    cudaFuncSetAttribute(hgemm_split<float>,
        cudaFuncAttributeMaxDynamicSharedMemorySize, HG_SMEM_BYTES);

    // ---- step-invariant precompute ----
    gather_emb<<<(NB_*TDEC_*E_ + 255)/256, 256>>>(y, emb, yemb);

    // NOTE: q bias b2 is folded in by adding it once into g_q? No — b2 is
    // constant per step; easiest: pre-add b2 into q inside decode? We instead
    // fold b2 into the keys GEMM? Simpler: add b2 to gxemb-like staging is not
    // possible; we add b2 by initializing g_q... q is overwritten each step,
    // so fold b2 into W2t path: add b2 during B staging is gone. Solution:
    // bake b2 into keys: score uses tanh(keys + q); q = h@W2 + b2 — equivalent
    // to keys' bias. Add b2 to b1 is wrong (different dims same DM). We bake it
    // into keysh: keys' = keys + b2 (broadcast over n,t); then q omits b2.
    // Implemented by passing (b1 + b2) as the keys-GEMM bias via a temp add.
    // b1 and b2 are both [DM]; keys + q + ... = x@W1 + b1 + h@W2 + b2.
    {
        // compute b1+b2 into g_yemb tail scratch (first 1024 floats are free
        // AFTER gather? not safe) — use g_ctxpart[0..1023] as scratch (unused
        // until decode loop runs).
        float* btmp;
        cudaGetSymbolAddress((void**)&btmp, g_ctxpart);
        // small add kernel via split_bf16? write a lambda-free approach:
        // reuse f32_to_f16? Simplest: tiny dedicated kernel below.
        extern __global__ void add_bias(const float*, const float*, float*);
        add_bias<<<4, 256>>>(b1, b2, btmp);
        split_bf16<<<(16000*1024/4 + 255)/256, 256>>>(x,  Ah, Al, 16000*1024/4);
        split_bf16<<<(1024*1024/4  + 255)/256, 256>>>(W1, Bh, Bl, 1024*1024/4);
        hgemm_split<__half><<<dim3(16000/128, 1024/128), 256, HG_SMEM_BYTES>>>(
            Ah, Al, Bh, Bl, btmp, keysh, 16000, 1024, 1024);
    }

    split_bf16<<<(3200*256/4 + 255)/256, 256>>>(yemb, Ah, Al, 3200*256/4);
    split_bf16<<<(256*3072/4 + 255)/256, 256>>>(Wx + (size_t)1024*G3_, Bh, Bl,
                                                256*3072/4);
    hgemm_split<float><<<dim3(3200/128, 3072/128), 256, HG_SMEM_BYTES>>>(
        Ah, Al, Bh, Bl, b_in, gxemb, 3200, 3072, 256);

    transpose_f16<<<dim3(1024/32, 1024/32), dim3(32,8)>>>(W2, W2t, 1024, 1024);
    transpose_f16<<<dim3(3072/32, 1024/32), dim3(32,8)>>>(Wx, Wxt, 1024, 3072);
    f32_to_f16<<<(NB_*TENC_*D_/4 + 255)/256, 256>>>(x, xh, NB_*TENC_*D_/4);

    // ---- persistent grouped decode loop ----
    decode_loop<<<GROUPS*BPG, 256>>>(m, v, bv, b_rec);

    // ---- out = H @ Wo + bo via split-bf16 tensor cores ----
    split_bf16<<<(3200*1024/4 + 255)/256, 256>>>(H,  Ah, Al, 3200*1024/4);
    split_bf16<<<(1024*8000/4 + 255)/256, 256>>>(Wo, Bh, Bl, 1024*8000/4);
    hgemm_split<float><<<dim3(3200/128, (8000 + 127)/128), 256, HG_SMEM_BYTES>>>(
        Ah, Al, Bh, Bl, bo, out, 3200, 8000, 1024);
}

// b1 + b2 elementwise (1024 elems) — folds q's bias into keys
__global__ void add_bias(const float* __restrict__ a, const float* __restrict__ b,
                         float* __restrict__ c)
{
    int i = blockIdx.x * blockDim.x + threadIdx.x;
    if (i < 1024) c[i] = a[i] + b[i];
}

// round 12
// speedup vs baseline: 1.1523x; 1.1523x over previous
#include <cuda_runtime.h>
#include <cuda_fp16.h>
#include <cuda_bf16.h>
#include <cstdint>

#define NB_   32
#define TENC_ 500
#define D_    1024
#define DM_   1024
#define TDEC_ 100
#define E_    256
#define C_    8000
#define G3_   (3*DM_)   // 3072

// ---------------- scratch (device globals; no allocations allowed) ----------
__device__ __half g_keysh[NB_*TENC_*DM_];    // 32.8 MB fp16
__device__ __half g_xh[NB_*TENC_*D_];        // 32.8 MB fp16 copy of x
__device__ __half g_W2t[DM_*DM_];            // W2^T fp16 [j][k]
__device__ __half g_Wxt[G3_*DM_];            // Wx^T (context rows) fp16 [j][k]
__device__ float g_yemb[NB_*TDEC_*E_];
__device__ float g_gxemb[NB_*TDEC_*G3_];     // 39.3 MB
__device__ float g_qpart[4*NB_*DM_];
__device__ float g_scores[NB_*TENC_];
__device__ float g_ctxpart[4*NB_*D_];
__device__ float g_gxp[4*3*NB_*DM_];         // [kz][gate][n][unit]
__device__ int   g_ugcnt[32];
__device__ float g_h[NB_*DM_];
__device__ float g_H[NB_*TDEC_*DM_];         // 13.1 MB
// split-bf16 staging for tensor-core GEMMs
__device__ __nv_bfloat16 g_Ah[16000*1024];
__device__ __nv_bfloat16 g_Al[16000*1024];
__device__ __nv_bfloat16 g_Bh[1024*8000];
__device__ __nv_bfloat16 g_Bl[1024*8000];

__device__ __forceinline__ float tanh_approx(float x) {
    float y;
    asm("tanh.approx.f32 %0, %1;" : "=f"(y) : "f"(x));
    return y;
}

// ---------------- tensor-core / async-copy primitives ------------------------
__device__ __forceinline__ void ldsm4(uint32_t* r, uint32_t addr) {
    asm volatile("ldmatrix.sync.aligned.m8n8.x4.shared.b16 {%0,%1,%2,%3}, [%4];"
        : "=r"(r[0]), "=r"(r[1]), "=r"(r[2]), "=r"(r[3]) : "r"(addr));
}
__device__ __forceinline__ void ldsm4t(uint32_t* r, uint32_t addr) {
    asm volatile("ldmatrix.sync.aligned.m8n8.x4.trans.shared.b16 {%0,%1,%2,%3}, [%4];"
        : "=r"(r[0]), "=r"(r[1]), "=r"(r[2]), "=r"(r[3]) : "r"(addr));
}
__device__ __forceinline__ void mma16816(float* c, const uint32_t* a, const uint32_t* b) {
    asm volatile("mma.sync.aligned.m16n8k16.row.col.f32.bf16.bf16.f32 "
        "{%0,%1,%2,%3},{%4,%5,%6,%7},{%8,%9},{%0,%1,%2,%3};"
        : "+f"(c[0]), "+f"(c[1]), "+f"(c[2]), "+f"(c[3])
        : "r"(a[0]), "r"(a[1]), "r"(a[2]), "r"(a[3]), "r"(b[0]), "r"(b[1]));
}
__device__ __forceinline__ void cpa16(uint32_t dst, const void* src) {
    asm volatile("cp.async.cg.shared.global [%0], [%1], 16;" :: "r"(dst), "l"(src));
}
__device__ __forceinline__ void cpa16z(uint32_t dst, const void* src, bool ok) {
    int sz = ok ? 16 : 0;
    asm volatile("cp.async.cg.shared.global [%0], [%1], 16, %2;"
                 :: "r"(dst), "l"(src), "r"(sz));
}

// ---------------- split fp32 -> (bf16 hi, bf16 lo) ---------------------------
__global__ void split_bf16(const float* __restrict__ src,
                           __nv_bfloat16* __restrict__ hi,
                           __nv_bfloat16* __restrict__ lo, int n4)
{
    int i = blockIdx.x * blockDim.x + threadIdx.x;
    if (i < n4) {
        float4 v = ((const float4*)src)[i];
        __nv_bfloat16 h0 = __float2bfloat16(v.x);
        __nv_bfloat16 h1 = __float2bfloat16(v.y);
        __nv_bfloat16 h2 = __float2bfloat16(v.z);
        __nv_bfloat16 h3 = __float2bfloat16(v.w);
        __nv_bfloat162 hh0; hh0.x = h0; hh0.y = h1;
        __nv_bfloat162 hh1; hh1.x = h2; hh1.y = h3;
        ((__nv_bfloat162*)hi)[2*i]   = hh0;
        ((__nv_bfloat162*)hi)[2*i+1] = hh1;
        __nv_bfloat162 ll0, ll1;
        ll0.x = __float2bfloat16(v.x - __bfloat162float(h0));
        ll0.y = __float2bfloat16(v.y - __bfloat162float(h1));
        ll1.x = __float2bfloat16(v.z - __bfloat162float(h2));
        ll1.y = __float2bfloat16(v.w - __bfloat162float(h3));
        ((__nv_bfloat162*)lo)[2*i]   = ll0;
        ((__nv_bfloat162*)lo)[2*i+1] = ll1;
    }
}

// ---------------- split-bf16 tensor-core GEMM, cp.async double-buffered ------
#define HG_BUF_ELEMS 18944
#define HG_SMEM_BYTES (2 * HG_BUF_ELEMS * 2)
template <typename OutT>
__global__ __launch_bounds__(256, 2) void hgemm_split(
    const __nv_bfloat16* __restrict__ Ah, const __nv_bfloat16* __restrict__ Al,
    const __nv_bfloat16* __restrict__ Bh, const __nv_bfloat16* __restrict__ Bl,
    const float* __restrict__ bias, OutT* __restrict__ C,
    int M, int N, int K)
{
    extern __shared__ __nv_bfloat16 smem_hg[];
    const uint32_t sbase = (uint32_t)__cvta_generic_to_shared(smem_hg);

    const int m0 = blockIdx.x * 128;
    const int n0 = blockIdx.y * 128;
    const int tid = threadIdx.x;
    const int wid = tid >> 5, lane = tid & 31;
    const int wm = wid >> 2, wn = wid & 3;

    float acc[4][4][4] = {};

    const int arow = tid >> 2;
    const int acol = (tid & 3) * 8;
    const int bk   = tid >> 4;
    const int bcol = (tid & 15) * 8;
    const bool bok = (n0 + bcol) < N;

    const int nk = K >> 5;

    auto loadTile = [&](int buf, int k0) {
        const uint32_t b0 = sbase + (uint32_t)buf * (HG_BUF_ELEMS * 2);
        cpa16(b0 + (uint32_t)((arow*40 + acol) * 2),
              Ah + (size_t)(m0 + arow) * K + k0 + acol);
        cpa16(b0 + (uint32_t)(((arow+64)*40 + acol) * 2),
              Ah + (size_t)(m0 + arow + 64) * K + k0 + acol);
        const uint32_t l0 = b0 + 5120*2;
        cpa16(l0 + (uint32_t)((arow*40 + acol) * 2),
              Al + (size_t)(m0 + arow) * K + k0 + acol);
        cpa16(l0 + (uint32_t)(((arow+64)*40 + acol) * 2),
              Al + (size_t)(m0 + arow + 64) * K + k0 + acol);
        const uint32_t bh0 = b0 + 10240*2;
        cpa16z(bh0 + (uint32_t)((bk*136 + bcol) * 2),
               Bh + (size_t)(k0 + bk) * N + n0 + bcol, bok);
        cpa16z(bh0 + (uint32_t)(((bk+16)*136 + bcol) * 2),
               Bh + (size_t)(k0 + bk + 16) * N + n0 + bcol, bok);
        const uint32_t bl0 = b0 + 14592*2;
        cpa16z(bl0 + (uint32_t)((bk*136 + bcol) * 2),
               Bl + (size_t)(k0 + bk) * N + n0 + bcol, bok);
        cpa16z(bl0 + (uint32_t)(((bk+16)*136 + bcol) * 2),
               Bl + (size_t)(k0 + bk + 16) * N + n0 + bcol, bok);
        asm volatile("cp.async.commit_group;");
    };

    loadTile(0, 0);

    for (int kt = 0; kt < nk; kt++) {
        const int buf = kt & 1;
        if (kt + 1 < nk) {
            loadTile(buf ^ 1, (kt + 1) << 5);
            asm volatile("cp.async.wait_group 1;");
        } else {
            asm volatile("cp.async.wait_group 0;");
        }
        __syncthreads();

        const uint32_t bb = sbase + (uint32_t)buf * (HG_BUF_ELEMS * 2);
        const uint32_t as_h = bb;
        const uint32_t as_l = bb + 10240;
        const uint32_t bs_h = bb + 20480;
        const uint32_t bs_l = bb + 29184;

#pragma unroll
        for (int kk = 0; kk < 32; kk += 16) {
            uint32_t ah[4][4], al[4][4], bh[4][2], bl[4][2];
#pragma unroll
            for (int mt = 0; mt < 4; mt++) {
                const uint32_t off =
                    (uint32_t)(((wm*64 + mt*16 + (lane & 15)) * 40
                                + kk + ((lane >> 4) << 3)) << 1);
                ldsm4(ah[mt], as_h + off);
                ldsm4(al[mt], as_l + off);
            }
#pragma unroll
            for (int ng = 0; ng < 2; ng++) {
                const uint32_t off =
                    (uint32_t)((((kk + (lane & 15)) * 136)
                                + wn*32 + ng*16 + ((lane >> 4) << 3)) << 1);
                uint32_t r[4];
                ldsm4t(r, bs_h + off);
                bh[2*ng][0] = r[0]; bh[2*ng][1] = r[1];
                bh[2*ng+1][0] = r[2]; bh[2*ng+1][1] = r[3];
                ldsm4t(r, bs_l + off);
                bl[2*ng][0] = r[0]; bl[2*ng][1] = r[1];
                bl[2*ng+1][0] = r[2]; bl[2*ng+1][1] = r[3];
            }
#pragma unroll
            for (int mt = 0; mt < 4; mt++)
#pragma unroll
                for (int nt = 0; nt < 4; nt++) {
                    mma16816(acc[mt][nt], ah[mt], bh[nt]);
                    mma16816(acc[mt][nt], ah[mt], bl[nt]);
                    mma16816(acc[mt][nt], al[mt], bh[nt]);
                }
        }
        __syncthreads();
    }

    const int tr = lane >> 2;
    const int tc = (lane & 3) * 2;
#pragma unroll
    for (int mt = 0; mt < 4; mt++) {
#pragma unroll
        for (int nt = 0; nt < 4; nt++) {
            const int col = n0 + wn*32 + nt*8 + tc;
            if (col < N) {
                const float b0 = bias[col], b1 = bias[col+1];
                const int r0 = m0 + wm*64 + mt*16 + tr;
                OutT* p0 = C + (size_t)r0 * N + col;
                OutT* p1 = C + (size_t)(r0 + 8) * N + col;
                p0[0] = (OutT)(acc[mt][nt][0] + b0);
                p0[1] = (OutT)(acc[mt][nt][1] + b1);
                p1[0] = (OutT)(acc[mt][nt][2] + b0);
                p1[1] = (OutT)(acc[mt][nt][3] + b1);
            }
        }
    }
}

// ---------------- transpose fp32 -> fp16 -------------------------------------
__global__ void transpose_f16(const float* __restrict__ src,
                              __half* __restrict__ dst,
                              int R, int ldsrc)
{
    __shared__ float tile[32][33];
    const int r0 = blockIdx.y * 32, c0 = blockIdx.x * 32;
    for (int i = threadIdx.y; i < 32; i += 8)
        tile[i][threadIdx.x] = src[(size_t)(r0 + i) * ldsrc + c0 + threadIdx.x];
    __syncthreads();
    for (int i = threadIdx.y; i < 32; i += 8)
        dst[(size_t)(c0 + i) * R + r0 + threadIdx.x] =
            __float2half(tile[threadIdx.x][i]);
}

// ---------------- fp32 -> fp16 bulk convert ---------------------------------
__global__ void f32_to_f16(const float* __restrict__ src,
                           __half* __restrict__ dst, int n4)
{
    int i = blockIdx.x * blockDim.x + threadIdx.x;
    if (i < n4) {
        float4 v = ((const float4*)src)[i];
        ((__half2*)dst)[2*i]   = __floats2half2_rn(v.x, v.y);
        ((__half2*)dst)[2*i+1] = __floats2half2_rn(v.z, v.w);
    }
}

// ---------------- embedding gather ------------------------------------------
__global__ void gather_emb(const int* __restrict__ y, const float* __restrict__ emb,
                           float* __restrict__ out)
{
    int idx = blockIdx.x * blockDim.x + threadIdx.x;
    if (idx < NB_*TDEC_*E_) {
        int row = idx >> 8;
        int e   = idx & 255;
        out[idx] = emb[(size_t)y[row] * E_ + e];
    }
}

// ---------------- skinny GEMM (q path) — PDL --------------------------------
__global__ __launch_bounds__(256) void gemm_skinny_h(
    const float* __restrict__ A, const __half* __restrict__ Bt,
    float* __restrict__ part, int NBcols)
{
    __shared__ float As[256][36];
    const int j0 = blockIdx.x * 32;
    const int kz = blockIdx.y;
    const int kbase = kz * 256;
    const int tid = threadIdx.x;

    cudaGridDependencySynchronize();

#pragma unroll 4
    for (int i = 0; i < 32; i++)
        As[tid][i] = A[(size_t)i * 1024 + kbase + tid];
    __syncthreads();

    const int tx = tid & 31, ty = tid >> 5;
    const int j = j0 + tx;
    const uint4* bp = (const uint4*)(Bt + (size_t)j * 1024 + kbase);

    float acc0 = 0.f, acc1 = 0.f, acc2 = 0.f, acc3 = 0.f;
#pragma unroll 4
    for (int kk = 0; kk < 256; kk += 8) {
        uint4 u = bp[kk >> 3];
        const __half2* hp = (const __half2*)&u;
        float b[8];
        float2 f0 = __half22float2(hp[0]); b[0] = f0.x; b[1] = f0.y;
        float2 f1 = __half22float2(hp[1]); b[2] = f1.x; b[3] = f1.y;
        float2 f2 = __half22float2(hp[2]); b[4] = f2.x; b[5] = f2.y;
        float2 f3 = __half22float2(hp[3]); b[6] = f3.x; b[7] = f3.y;
#pragma unroll
        for (int u8 = 0; u8 < 8; u8++) {
            float4 a = *(const float4*)&As[kk + u8][ty * 4];
            acc0 = fmaf(b[u8], a.x, acc0);
            acc1 = fmaf(b[u8], a.y, acc1);
            acc2 = fmaf(b[u8], a.z, acc2);
            acc3 = fmaf(b[u8], a.w, acc3);
        }
    }
    const int n = ty * 4;
    float* po = part + (size_t)(kz * 32 + n) * NBcols + j;
    po[0]                 = acc0;
    po[(size_t)NBcols]    = acc1;
    po[(size_t)2*NBcols]  = acc2;
    po[(size_t)3*NBcols]  = acc3;
    cudaTriggerProgrammaticLaunchCompletion();
}

// ---------------- score — cp.async staged keys, PDL ---------------------------
// grid (32, NB): block = (n, 16-row t-chunk). Keys staged via cp.async issued
// BEFORE the grid dependency sync (keys are step-invariant).
#define SC_ROWS 16
__global__ __launch_bounds__(256) void score_kernel(
    const float* __restrict__ b2, const float* __restrict__ v,
    const float* __restrict__ bv)
{
    __shared__ __align__(16) __half ks[SC_ROWS*1024];   // 32 KB
    __shared__ float qs[DM_];
    __shared__ float vs[DM_];
    const int n = blockIdx.y;
    const int t0 = blockIdx.x * SC_ROWS;
    const int tid = threadIdx.x;
    const int nrows = (t0 + SC_ROWS <= TENC_) ? SC_ROWS : (TENC_ - t0);

    // stage keys rows NOW — independent of predecessor kernel
    const uint32_t ks_addr = (uint32_t)__cvta_generic_to_shared(ks);
    const __half* ksrc = g_keysh + ((size_t)(n*TENC_ + t0) << 10);
    for (int idx = tid; idx < nrows*128; idx += 256)
        cpa16(ks_addr + idx*16, ksrc + (idx << 3));
    asm volatile("cp.async.commit_group;" ::: "memory");

    for (int d = tid; d < DM_; d += 256) vs[d] = v[d];
    const float bvv = bv[0];

    cudaGridDependencySynchronize();

    for (int d = tid; d < DM_; d += 256) {
        float s = b2[d];
#pragma unroll
        for (int sp = 0; sp < 4; sp++) s += g_qpart[sp*NB_*DM_ + n*DM_ + d];
        qs[d] = s;
    }
    asm volatile("cp.async.wait_group 0;" ::: "memory");
    __syncthreads();

    const int w = tid >> 5, lane = tid & 31;
    for (int r = w; r < nrows; r += 8) {
        const __half* kp = ks + r*1024;
        float acc = 0.f;
#pragma unroll
        for (int i = 0; i < 4; i++) {
            uint4 u = *(const uint4*)(kp + ((lane + (i << 5)) << 3));
            const __half2* hp = (const __half2*)&u;
            const int d0 = (lane + (i << 5)) << 3;
            float4 q1 = *(const float4*)&qs[d0];
            float4 q2 = *(const float4*)&qs[d0 + 4];
            float4 v1 = *(const float4*)&vs[d0];
            float4 v2 = *(const float4*)&vs[d0 + 4];
            float2 f0 = __half22float2(hp[0]);
            float2 f1 = __half22float2(hp[1]);
            float2 f2 = __half22float2(hp[2]);
            float2 f3 = __half22float2(hp[3]);
            acc = fmaf(tanh_approx(f0.x + q1.x), v1.x, acc);
            acc = fmaf(tanh_approx(f0.y + q1.y), v1.y, acc);
            acc = fmaf(tanh_approx(f1.x + q1.z), v1.z, acc);
            acc = fmaf(tanh_approx(f1.y + q1.w), v1.w, acc);
            acc = fmaf(tanh_approx(f2.x + q2.x), v2.x, acc);
            acc = fmaf(tanh_approx(f2.y + q2.y), v2.y, acc);
            acc = fmaf(tanh_approx(f3.x + q2.z), v2.z, acc);
            acc = fmaf(tanh_approx(f3.y + q2.w), v2.w, acc);
        }
#pragma unroll
        for (int off = 16; off; off >>= 1)
            acc += __shfl_xor_sync(0xffffffffu, acc, off);
        if (lane == 0) g_scores[n*TENC_ + t0 + r] = acc + bvv;
    }
    cudaTriggerProgrammaticLaunchCompletion();
}

// ---------------- softmax + context — cp.async pipelined x, PDL --------------
// grid (4 dc, 4 tc, 32 n). x rows staged in a 4-stage, 16-row pipeline
// issued before the grid sync; softmax overlaps the in-flight loads.
#define CXR 16
__global__ __launch_bounds__(256) void context_part(void)
{
    __shared__ __align__(16) __half xs[4][CXR*256];   // 32 KB
    __shared__ float ws[TENC_];
    __shared__ float red[256];
    const int n  = blockIdx.z;
    const int tc = blockIdx.y;
    const int dc = blockIdx.x;
    const int tid = threadIdx.x;
    const int tt0 = tc * 125;

    const uint32_t xs_addr = (uint32_t)__cvta_generic_to_shared(&xs[0][0]);
    auto issue = [&](int s) {
        const int r0 = s * CXR;
        const int cnt = (r0 + CXR <= 125) ? CXR : (r0 < 125 ? 125 - r0 : 0);
        if (cnt > 0) {
            const uint32_t dst = xs_addr + (uint32_t)(s & 3) * (CXR*512);
            const __half* src = g_xh + ((size_t)(n*TENC_ + tt0 + r0) << 10) + dc*256;
            for (int idx = tid; idx < cnt*32; idx += 256) {
                const int row = idx >> 5, c = idx & 31;
                cpa16(dst + row*512 + c*16, src + ((size_t)row << 10) + (c << 3));
            }
        }
        asm volatile("cp.async.commit_group;" ::: "memory");
    };
    issue(0); issue(1); issue(2); issue(3);

    cudaGridDependencySynchronize();

    float mx = -1e30f;
    for (int t = tid; t < TENC_; t += 256) {
        float s = g_scores[n*TENC_ + t];
        ws[t] = s;
        mx = fmaxf(mx, s);
    }
    red[tid] = mx; __syncthreads();
    for (int s = 128; s; s >>= 1) {
        if (tid < s) red[tid] = fmaxf(red[tid], red[tid+s]);
        __syncthreads();
    }
    mx = red[0];
    __syncthreads();
    float lsum = 0.f;
    for (int t = tid; t < TENC_; t += 256) {
        float e = __expf(ws[t] - mx);
        ws[t] = e;
        lsum += e;
    }
    red[tid] = lsum; __syncthreads();
    for (int s = 128; s; s >>= 1) {
        if (tid < s) red[tid] += red[tid+s];
        __syncthreads();
    }
    const float inv = 1.f / red[0];

    float a0 = 0.f, a1 = 0.f, a2 = 0.f, a3 = 0.f;
    for (int s = 0; s < 8; s++) {
        asm volatile("cp.async.wait_group 3;" ::: "memory");
        __syncthreads();
        const __half* xp = &xs[s & 3][0];
        const int cnt = (s*CXR + CXR <= 125) ? CXR : (125 - s*CXR);  // last = 13
        const float* wp = ws + tt0 + s*CXR;
        int row = 0;
        for (; row + 4 <= cnt; row += 4) {
            a0 = fmaf(wp[row+0], __half2float(xp[(row+0)*256 + tid]), a0);
            a1 = fmaf(wp[row+1], __half2float(xp[(row+1)*256 + tid]), a1);
            a2 = fmaf(wp[row+2], __half2float(xp[(row+2)*256 + tid]), a2);
            a3 = fmaf(wp[row+3], __half2float(xp[(row+3)*256 + tid]), a3);
        }
        for (; row < cnt; row++)
            a0 = fmaf(wp[row], __half2float(xp[row*256 + tid]), a0);
        __syncthreads();
        issue(s + 4);   // empty commits keep group accounting uniform
    }

    g_ctxpart[((size_t)tc * NB_ + n) * D_ + dc*256 + tid] =
        ((a0 + a1) + (a2 + a3)) * inv;
    cudaTriggerProgrammaticLaunchCompletion();
}

// ---------------- fused gx-GEMM + GRU gate — PDL ------------------------------
__global__ __launch_bounds__(256) void gxgate_kernel(
    const float* __restrict__ b_rec, int t)
{
    __shared__ float As[256][36];
    __shared__ int last_flag;
    const int ug = blockIdx.x;
    const int kz = blockIdx.y;
    const int kbase = kz * 256;
    const int tid = threadIdx.x;

    cudaGridDependencySynchronize();

#pragma unroll 4
    for (int i = 0; i < 32; i++) {
        float s = g_ctxpart[(size_t)i * 1024 + kbase + tid];
#pragma unroll
        for (int p = 1; p < 4; p++)
            s += g_ctxpart[(size_t)p * (NB_*D_) + (size_t)i * 1024 + kbase + tid];
        As[tid][i] = s;
    }
    __syncthreads();

    const int tx = tid & 31, ty = tid >> 5;
    const int unit = ug * 32 + tx;
    const uint4* bz = (const uint4*)(g_Wxt + (size_t)unit          * 1024 + kbase);
    const uint4* br = (const uint4*)(g_Wxt + (size_t)(1024 + unit) * 1024 + kbase);
    const uint4* bh = (const uint4*)(g_Wxt + (size_t)(2048 + unit) * 1024 + kbase);

    float az[4] = {}, ar[4] = {}, ah[4] = {};
#pragma unroll 2
    for (int kk = 0; kk < 256; kk += 8) {
        uint4 uz = bz[kk >> 3], ur = br[kk >> 3], uh = bh[kk >> 3];
        const __half2 *hz = (const __half2*)&uz, *hr = (const __half2*)&ur,
                      *hhp = (const __half2*)&uh;
        float wz[8], wr[8], wh[8];
#pragma unroll
        for (int p = 0; p < 4; p++) {
            float2 fz = __half22float2(hz[p]);  wz[2*p] = fz.x; wz[2*p+1] = fz.y;
            float2 fr = __half22float2(hr[p]);  wr[2*p] = fr.x; wr[2*p+1] = fr.y;
            float2 fh = __half22float2(hhp[p]); wh[2*p] = fh.x; wh[2*p+1] = fh.y;
        }
#pragma unroll
        for (int u8 = 0; u8 < 8; u8++) {
            float4 a = *(const float4*)&As[kk + u8][ty * 4];
#pragma unroll
            for (int i = 0; i < 4; i++) {
                float av = (&a.x)[i];
                az[i] = fmaf(wz[u8], av, az[i]);
                ar[i] = fmaf(wr[u8], av, ar[i]);
                ah[i] = fmaf(wh[u8], av, ah[i]);
            }
        }
    }

#pragma unroll
    for (int i = 0; i < 4; i++) {
        const int n = ty * 4 + i;
        g_gxp[((size_t)(kz*3 + 0) * NB_ + n) * DM_ + unit] = az[i];
        g_gxp[((size_t)(kz*3 + 1) * NB_ + n) * DM_ + unit] = ar[i];
        g_gxp[((size_t)(kz*3 + 2) * NB_ + n) * DM_ + unit] = ah[i];
    }
    __threadfence();
    __syncthreads();
    if (tid == 0)
        last_flag = (atomicAdd(&g_ugcnt[ug], 1) == 3);
    __syncthreads();

    if (last_flag) {
        __threadfence();
        const float brz = b_rec[unit];
        const float brr = b_rec[unit + 1024];
        const float brh = b_rec[unit + 2048];
#pragma unroll
        for (int i = 0; i < 4; i++) {
            const int n = ty * 4 + i;
            float xz = 0.f, xr = 0.f, xh = 0.f;
#pragma unroll
            for (int z = 0; z < 4; z++) {
                xz += g_gxp[((size_t)(z*3 + 0) * NB_ + n) * DM_ + unit];
                xr += g_gxp[((size_t)(z*3 + 1) * NB_ + n) * DM_ + unit];
                xh += g_gxp[((size_t)(z*3 + 2) * NB_ + n) * DM_ + unit];
            }
            const float* ge = g_gxemb + (size_t)(n*TDEC_ + t) * G3_;
            xz += ge[unit]; xr += ge[unit + 1024]; xh += ge[unit + 2048];

            float zg = 1.f / (1.f + __expf(-(xz + brz)));
            float rg = 1.f / (1.f + __expf(-(xr + brr)));
            float hg = tanhf(xh + rg * brh);
            float hv = (1.f - zg) * hg;

            g_h[n * DM_ + unit] = hv;
            g_H[(size_t)(n*TDEC_ + t) * DM_ + unit] = hv;
        }
        __syncthreads();
        if (tid == 0) g_ugcnt[ug] = 0;
    }
}

// ---------------- PDL launch helper ------------------------------------------
template <typename F, typename... Args>
static inline void launch_pdl(dim3 g, dim3 b, F f, Args... args)
{
    cudaLaunchAttribute attr;
    attr.id = cudaLaunchAttributeProgrammaticStreamSerialization;
    attr.val.programmaticStreamSerializationAllowed = 1;
    cudaLaunchConfig_t cfg = {};
    cfg.gridDim = g; cfg.blockDim = b;
    cfg.dynamicSmemBytes = 0;
    cfg.stream = 0;
    cfg.attrs = &attr; cfg.numAttrs = 1;
    cudaLaunchKernelEx(&cfg, f, args...);
}

// ---------------- launch -----------------------------------------------------
extern "C" void kernel_launch(void* const* d_in, const int* in_sizes, int n_in,
                              void* d_out, int out_size)
{
    (void)in_sizes; (void)n_in; (void)out_size;
    const float* x    = (const float*)d_in[0];
    const float* m    = (const float*)d_in[1];
    const int*   y    = (const int*)  d_in[2];
    const float* emb  = (const float*)d_in[3];
    const float* W1   = (const float*)d_in[4];
    const float* b1   = (const float*)d_in[5];
    const float* W2   = (const float*)d_in[6];
    const float* b2   = (const float*)d_in[7];
    const float* v    = (const float*)d_in[8];
    const float* bv   = (const float*)d_in[9];
    const float* Wx   = (const float*)d_in[10];
    // d_in[11] = Uh — provably unused (h_prev == 0)
    const float* b_in = (const float*)d_in[12];
    const float* b_rec= (const float*)d_in[13];
    const float* Wo   = (const float*)d_in[14];
    const float* bo   = (const float*)d_in[15];
    float* out = (float*)d_out;

    __half *keysh, *xh, *W2t, *Wxt;
    __nv_bfloat16 *Ah, *Al, *Bh, *Bl;
    float *yemb, *gxemb, *qpart, *h, *H;
    cudaGetSymbolAddress((void**)&keysh,  g_keysh);
    cudaGetSymbolAddress((void**)&xh,     g_xh);
    cudaGetSymbolAddress((void**)&W2t,    g_W2t);
    cudaGetSymbolAddress((void**)&Wxt,    g_Wxt);
    cudaGetSymbolAddress((void**)&yemb,   g_yemb);
    cudaGetSymbolAddress((void**)&gxemb,  g_gxemb);
    cudaGetSymbolAddress((void**)&qpart,  g_qpart);
    cudaGetSymbolAddress((void**)&h,      g_h);
    cudaGetSymbolAddress((void**)&H,      g_H);
    cudaGetSymbolAddress((void**)&Ah,     g_Ah);
    cudaGetSymbolAddress((void**)&Al,     g_Al);
    cudaGetSymbolAddress((void**)&Bh,     g_Bh);
    cudaGetSymbolAddress((void**)&Bl,     g_Bl);

    cudaFuncSetAttribute(hgemm_split<__half>,
        cudaFuncAttributeMaxDynamicSharedMemorySize, HG_SMEM_BYTES);
    cudaFuncSetAttribute(hgemm_split<float>,
        cudaFuncAttributeMaxDynamicSharedMemorySize, HG_SMEM_BYTES);

    // ---- step-invariant precompute ----
    gather_emb<<<(NB_*TDEC_*E_ + 255)/256, 256>>>(y, emb, yemb);

    split_bf16<<<(16000*1024/4 + 255)/256, 256>>>(x,  Ah, Al, 16000*1024/4);
    split_bf16<<<(1024*1024/4  + 255)/256, 256>>>(W1, Bh, Bl, 1024*1024/4);
    hgemm_split<__half><<<dim3(16000/128, 1024/128), 256, HG_SMEM_BYTES>>>(
        Ah, Al, Bh, Bl, b1, keysh, 16000, 1024, 1024);

    split_bf16<<<(3200*256/4 + 255)/256, 256>>>(yemb, Ah, Al, 3200*256/4);
    split_bf16<<<(256*3072/4 + 255)/256, 256>>>(Wx + (size_t)1024*G3_, Bh, Bl,
                                                256*3072/4);
    hgemm_split<float><<<dim3(3200/128, 3072/128), 256, HG_SMEM_BYTES>>>(
        Ah, Al, Bh, Bl, b_in, gxemb, 3200, 3072, 256);

    transpose_f16<<<dim3(1024/32, 1024/32), dim3(32,8)>>>(W2, W2t, 1024, 1024);
    transpose_f16<<<dim3(3072/32, 1024/32), dim3(32,8)>>>(Wx, Wxt, 1024, 3072);
    f32_to_f16<<<(NB_*TENC_*D_/4 + 255)/256, 256>>>(x, xh, NB_*TENC_*D_/4);
    cudaMemcpyAsync(h, m, (size_t)NB_*DM_*sizeof(float), cudaMemcpyDeviceToDevice);

    // ---- sequential decode loop (4 PDL kernels/step) ----
    for (int t = 0; t < TDEC_; t++) {
        launch_pdl(dim3(DM_/32, 4), dim3(256), gemm_skinny_h,
                   (const float*)h, (const __half*)W2t, qpart, (int)DM_);
        launch_pdl(dim3((TENC_ + SC_ROWS - 1)/SC_ROWS, NB_), dim3(256),
                   score_kernel, b2, v, bv);
        launch_pdl(dim3(4, 4, NB_), dim3(256), context_part);
        launch_pdl(dim3(32, 4), dim3(256), gxgate_kernel, b_rec, t);
    }

    // ---- out = H @ Wo + bo via split-bf16 tensor cores ----
    split_bf16<<<(3200*1024/4 + 255)/256, 256>>>(H,  Ah, Al, 3200*1024/4);
    split_bf16<<<(1024*8000/4 + 255)/256, 256>>>(Wo, Bh, Bl, 1024*8000/4);
    hgemm_split<float><<<dim3(3200/128, (8000 + 127)/128), 256, HG_SMEM_BYTES>>>(
        Ah, Al, Bh, Bl, bo, out, 3200, 8000, 1024);
}

// round 13
// speedup vs baseline: 1.2631x; 1.0962x over previous
#include <cuda_runtime.h>
#include <cuda_fp16.h>
#include <cuda_bf16.h>
#include <cstdint>

#define NB_   32
#define TENC_ 500
#define D_    1024
#define DM_   1024
#define TDEC_ 100
#define E_    256
#define C_    8000
#define G3_   (3*DM_)   // 3072

// ---------------- scratch (device globals; no allocations allowed) ----------
__device__ __half g_keysh[NB_*TENC_*DM_];    // 32.8 MB fp16
__device__ __half g_xh[NB_*TENC_*D_];        // 32.8 MB fp16 copy of x
__device__ __half g_W2t[DM_*DM_];            // W2^T fp16 [j][k]
__device__ __half g_Wxt[G3_*DM_];            // Wx^T (context rows) fp16 [j][k]
__device__ float g_yemb[NB_*TDEC_*E_];
__device__ float g_gxemb[NB_*TDEC_*G3_];     // 39.3 MB
__device__ float g_qpart[4*NB_*DM_];
__device__ float g_scores[NB_*TENC_];
__device__ float g_ctxpart[4*NB_*D_];
__device__ float g_gxp[4*3*NB_*DM_];         // [kz][gate][n][unit]
__device__ int   g_ugcnt[32];
__device__ float g_h[NB_*DM_];
__device__ float g_H[NB_*TDEC_*DM_];         // 13.1 MB
// split-bf16 staging for tensor-core GEMMs
__device__ __nv_bfloat16 g_Ah[16000*1024];
__device__ __nv_bfloat16 g_Al[16000*1024];
__device__ __nv_bfloat16 g_Bh[1024*8000];
__device__ __nv_bfloat16 g_Bl[1024*8000];

__device__ __forceinline__ float tanh_approx(float x) {
    float y;
    asm("tanh.approx.f32 %0, %1;" : "=f"(y) : "f"(x));
    return y;
}

// ---------------- tensor-core / async-copy primitives ------------------------
__device__ __forceinline__ void ldsm4(uint32_t* r, uint32_t addr) {
    asm volatile("ldmatrix.sync.aligned.m8n8.x4.shared.b16 {%0,%1,%2,%3}, [%4];"
        : "=r"(r[0]), "=r"(r[1]), "=r"(r[2]), "=r"(r[3]) : "r"(addr));
}
__device__ __forceinline__ void ldsm4t(uint32_t* r, uint32_t addr) {
    asm volatile("ldmatrix.sync.aligned.m8n8.x4.trans.shared.b16 {%0,%1,%2,%3}, [%4];"
        : "=r"(r[0]), "=r"(r[1]), "=r"(r[2]), "=r"(r[3]) : "r"(addr));
}
__device__ __forceinline__ void mma16816(float* c, const uint32_t* a, const uint32_t* b) {
    asm volatile("mma.sync.aligned.m16n8k16.row.col.f32.bf16.bf16.f32 "
        "{%0,%1,%2,%3},{%4,%5,%6,%7},{%8,%9},{%0,%1,%2,%3};"
        : "+f"(c[0]), "+f"(c[1]), "+f"(c[2]), "+f"(c[3])
        : "r"(a[0]), "r"(a[1]), "r"(a[2]), "r"(a[3]), "r"(b[0]), "r"(b[1]));
}
__device__ __forceinline__ void cpa16(uint32_t dst, const void* src) {
    asm volatile("cp.async.cg.shared.global [%0], [%1], 16;" :: "r"(dst), "l"(src));
}
__device__ __forceinline__ void cpa16z(uint32_t dst, const void* src, bool ok) {
    int sz = ok ? 16 : 0;
    asm volatile("cp.async.cg.shared.global [%0], [%1], 16, %2;"
                 :: "r"(dst), "l"(src), "r"(sz));
}

// ---------------- split fp32 -> (bf16 hi, bf16 lo) ---------------------------
__global__ void split_bf16(const float* __restrict__ src,
                           __nv_bfloat16* __restrict__ hi,
                           __nv_bfloat16* __restrict__ lo, int n4)
{
    int i = blockIdx.x * blockDim.x + threadIdx.x;
    if (i < n4) {
        float4 v = ((const float4*)src)[i];
        __nv_bfloat16 h0 = __float2bfloat16(v.x);
        __nv_bfloat16 h1 = __float2bfloat16(v.y);
        __nv_bfloat16 h2 = __float2bfloat16(v.z);
        __nv_bfloat16 h3 = __float2bfloat16(v.w);
        __nv_bfloat162 hh0; hh0.x = h0; hh0.y = h1;
        __nv_bfloat162 hh1; hh1.x = h2; hh1.y = h3;
        ((__nv_bfloat162*)hi)[2*i]   = hh0;
        ((__nv_bfloat162*)hi)[2*i+1] = hh1;
        __nv_bfloat162 ll0, ll1;
        ll0.x = __float2bfloat16(v.x - __bfloat162float(h0));
        ll0.y = __float2bfloat16(v.y - __bfloat162float(h1));
        ll1.x = __float2bfloat16(v.z - __bfloat162float(h2));
        ll1.y = __float2bfloat16(v.w - __bfloat162float(h3));
        ((__nv_bfloat162*)lo)[2*i]   = ll0;
        ((__nv_bfloat162*)lo)[2*i+1] = ll1;
    }
}

// ---------------- split-bf16 tensor-core GEMM, cp.async double-buffered ------
#define HG_BUF_ELEMS 18944
#define HG_SMEM_BYTES (2 * HG_BUF_ELEMS * 2)
template <typename OutT>
__global__ __launch_bounds__(256, 2) void hgemm_split(
    const __nv_bfloat16* __restrict__ Ah, const __nv_bfloat16* __restrict__ Al,
    const __nv_bfloat16* __restrict__ Bh, const __nv_bfloat16* __restrict__ Bl,
    const float* __restrict__ bias, OutT* __restrict__ C,
    int M, int N, int K)
{
    extern __shared__ __nv_bfloat16 smem_hg[];
    const uint32_t sbase = (uint32_t)__cvta_generic_to_shared(smem_hg);

    const int m0 = blockIdx.x * 128;
    const int n0 = blockIdx.y * 128;
    const int tid = threadIdx.x;
    const int wid = tid >> 5, lane = tid & 31;
    const int wm = wid >> 2, wn = wid & 3;

    float acc[4][4][4] = {};

    const int arow = tid >> 2;
    const int acol = (tid & 3) * 8;
    const int bk   = tid >> 4;
    const int bcol = (tid & 15) * 8;
    const bool bok = (n0 + bcol) < N;

    const int nk = K >> 5;

    auto loadTile = [&](int buf, int k0) {
        const uint32_t b0 = sbase + (uint32_t)buf * (HG_BUF_ELEMS * 2);
        cpa16(b0 + (uint32_t)((arow*40 + acol) * 2),
              Ah + (size_t)(m0 + arow) * K + k0 + acol);
        cpa16(b0 + (uint32_t)(((arow+64)*40 + acol) * 2),
              Ah + (size_t)(m0 + arow + 64) * K + k0 + acol);
        const uint32_t l0 = b0 + 5120*2;
        cpa16(l0 + (uint32_t)((arow*40 + acol) * 2),
              Al + (size_t)(m0 + arow) * K + k0 + acol);
        cpa16(l0 + (uint32_t)(((arow+64)*40 + acol) * 2),
              Al + (size_t)(m0 + arow + 64) * K + k0 + acol);
        const uint32_t bh0 = b0 + 10240*2;
        cpa16z(bh0 + (uint32_t)((bk*136 + bcol) * 2),
               Bh + (size_t)(k0 + bk) * N + n0 + bcol, bok);
        cpa16z(bh0 + (uint32_t)(((bk+16)*136 + bcol) * 2),
               Bh + (size_t)(k0 + bk + 16) * N + n0 + bcol, bok);
        const uint32_t bl0 = b0 + 14592*2;
        cpa16z(bl0 + (uint32_t)((bk*136 + bcol) * 2),
               Bl + (size_t)(k0 + bk) * N + n0 + bcol, bok);
        cpa16z(bl0 + (uint32_t)(((bk+16)*136 + bcol) * 2),
               Bl + (size_t)(k0 + bk + 16) * N + n0 + bcol, bok);
        asm volatile("cp.async.commit_group;");
    };

    loadTile(0, 0);

    for (int kt = 0; kt < nk; kt++) {
        const int buf = kt & 1;
        if (kt + 1 < nk) {
            loadTile(buf ^ 1, (kt + 1) << 5);
            asm volatile("cp.async.wait_group 1;");
        } else {
            asm volatile("cp.async.wait_group 0;");
        }
        __syncthreads();

        const uint32_t bb = sbase + (uint32_t)buf * (HG_BUF_ELEMS * 2);
        const uint32_t as_h = bb;
        const uint32_t as_l = bb + 10240;
        const uint32_t bs_h = bb + 20480;
        const uint32_t bs_l = bb + 29184;

#pragma unroll
        for (int kk = 0; kk < 32; kk += 16) {
            uint32_t ah[4][4], al[4][4], bh[4][2], bl[4][2];
#pragma unroll
            for (int mt = 0; mt < 4; mt++) {
                const uint32_t off =
                    (uint32_t)(((wm*64 + mt*16 + (lane & 15)) * 40
                                + kk + ((lane >> 4) << 3)) << 1);
                ldsm4(ah[mt], as_h + off);
                ldsm4(al[mt], as_l + off);
            }
#pragma unroll
            for (int ng = 0; ng < 2; ng++) {
                const uint32_t off =
                    (uint32_t)((((kk + (lane & 15)) * 136)
                                + wn*32 + ng*16 + ((lane >> 4) << 3)) << 1);
                uint32_t r[4];
                ldsm4t(r, bs_h + off);
                bh[2*ng][0] = r[0]; bh[2*ng][1] = r[1];
                bh[2*ng+1][0] = r[2]; bh[2*ng+1][1] = r[3];
                ldsm4t(r, bs_l + off);
                bl[2*ng][0] = r[0]; bl[2*ng][1] = r[1];
                bl[2*ng+1][0] = r[2]; bl[2*ng+1][1] = r[3];
            }
#pragma unroll
            for (int mt = 0; mt < 4; mt++)
#pragma unroll
                for (int nt = 0; nt < 4; nt++) {
                    mma16816(acc[mt][nt], ah[mt], bh[nt]);
                    mma16816(acc[mt][nt], ah[mt], bl[nt]);
                    mma16816(acc[mt][nt], al[mt], bh[nt]);
                }
        }
        __syncthreads();
    }

    const int tr = lane >> 2;
    const int tc = (lane & 3) * 2;
#pragma unroll
    for (int mt = 0; mt < 4; mt++) {
#pragma unroll
        for (int nt = 0; nt < 4; nt++) {
            const int col = n0 + wn*32 + nt*8 + tc;
            if (col < N) {
                const float b0 = bias[col], b1 = bias[col+1];
                const int r0 = m0 + wm*64 + mt*16 + tr;
                OutT* p0 = C + (size_t)r0 * N + col;
                OutT* p1 = C + (size_t)(r0 + 8) * N + col;
                p0[0] = (OutT)(acc[mt][nt][0] + b0);
                p0[1] = (OutT)(acc[mt][nt][1] + b1);
                p1[0] = (OutT)(acc[mt][nt][2] + b0);
                p1[1] = (OutT)(acc[mt][nt][3] + b1);
            }
        }
    }
}

// ---------------- transpose fp32 -> fp16 -------------------------------------
__global__ void transpose_f16(const float* __restrict__ src,
                              __half* __restrict__ dst,
                              int R, int ldsrc)
{
    __shared__ float tile[32][33];
    const int r0 = blockIdx.y * 32, c0 = blockIdx.x * 32;
    for (int i = threadIdx.y; i < 32; i += 8)
        tile[i][threadIdx.x] = src[(size_t)(r0 + i) * ldsrc + c0 + threadIdx.x];
    __syncthreads();
    for (int i = threadIdx.y; i < 32; i += 8)
        dst[(size_t)(c0 + i) * R + r0 + threadIdx.x] =
            __float2half(tile[threadIdx.x][i]);
}

// ---------------- fp32 -> fp16 bulk convert ---------------------------------
__global__ void f32_to_f16(const float* __restrict__ src,
                           __half* __restrict__ dst, int n4)
{
    int i = blockIdx.x * blockDim.x + threadIdx.x;
    if (i < n4) {
        float4 v = ((const float4*)src)[i];
        ((__half2*)dst)[2*i]   = __floats2half2_rn(v.x, v.y);
        ((__half2*)dst)[2*i+1] = __floats2half2_rn(v.z, v.w);
    }
}

// ---------------- embedding gather ------------------------------------------
__global__ void gather_emb(const int* __restrict__ y, const float* __restrict__ emb,
                           float* __restrict__ out)
{
    int idx = blockIdx.x * blockDim.x + threadIdx.x;
    if (idx < NB_*TDEC_*E_) {
        int row = idx >> 8;
        int e   = idx & 255;
        out[idx] = emb[(size_t)y[row] * E_ + e];
    }
}

// ---------------- skinny GEMM (q path) — PDL --------------------------------
__global__ __launch_bounds__(256) void gemm_skinny_h(
    const float* __restrict__ A, const __half* __restrict__ Bt,
    float* __restrict__ part, int NBcols)
{
    __shared__ float As[256][36];
    const int j0 = blockIdx.x * 32;
    const int kz = blockIdx.y;
    const int kbase = kz * 256;
    const int tid = threadIdx.x;

    cudaGridDependencySynchronize();

#pragma unroll 4
    for (int i = 0; i < 32; i++)
        As[tid][i] = A[(size_t)i * 1024 + kbase + tid];
    __syncthreads();

    const int tx = tid & 31, ty = tid >> 5;
    const int j = j0 + tx;
    const uint4* bp = (const uint4*)(Bt + (size_t)j * 1024 + kbase);

    float acc0 = 0.f, acc1 = 0.f, acc2 = 0.f, acc3 = 0.f;
#pragma unroll 4
    for (int kk = 0; kk < 256; kk += 8) {
        uint4 u = bp[kk >> 3];
        const __half2* hp = (const __half2*)&u;
        float b[8];
        float2 f0 = __half22float2(hp[0]); b[0] = f0.x; b[1] = f0.y;
        float2 f1 = __half22float2(hp[1]); b[2] = f1.x; b[3] = f1.y;
        float2 f2 = __half22float2(hp[2]); b[4] = f2.x; b[5] = f2.y;
        float2 f3 = __half22float2(hp[3]); b[6] = f3.x; b[7] = f3.y;
#pragma unroll
        for (int u8 = 0; u8 < 8; u8++) {
            float4 a = *(const float4*)&As[kk + u8][ty * 4];
            acc0 = fmaf(b[u8], a.x, acc0);
            acc1 = fmaf(b[u8], a.y, acc1);
            acc2 = fmaf(b[u8], a.z, acc2);
            acc3 = fmaf(b[u8], a.w, acc3);
        }
    }
    const int n = ty * 4;
    float* po = part + (size_t)(kz * 32 + n) * NBcols + j;
    po[0]                 = acc0;
    po[(size_t)NBcols]    = acc1;
    po[(size_t)2*NBcols]  = acc2;
    po[(size_t)3*NBcols]  = acc3;
    cudaTriggerProgrammaticLaunchCompletion();
}

// ---------------- score — 4 rows/warp register pipeline, PDL ------------------
// grid (16, 32): block covers 32 t-rows (8 warps x 4 rows). 16 independent
// uint4 LDGs per thread in flight before the tanh chain.
__global__ __launch_bounds__(256) void score_kernel(
    const float* __restrict__ b2, const float* __restrict__ v,
    const float* __restrict__ bv)
{
    __shared__ float qs[DM_];
    __shared__ float vs[DM_];
    const int n = blockIdx.y;
    const int tid = threadIdx.x;
    const int w = tid >> 5, lane = tid & 31;
    const int r0 = blockIdx.x * 32 + w * 4;

    for (int d = tid; d < DM_; d += 256) vs[d] = v[d];
    const float bvv = bv[0];

    // issue all 16 independent keys loads (keys are step-invariant; legal
    // before the dependency sync)
    int rr[4];
#pragma unroll
    for (int j = 0; j < 4; j++) {
        int r = r0 + j;
        rr[j] = (r < TENC_) ? r : (TENC_ - 1);
    }
    uint4 u[4][4];
#pragma unroll
    for (int j = 0; j < 4; j++) {
        const uint4* kp = (const uint4*)(g_keysh + ((size_t)(n*TENC_ + rr[j]) << 10));
#pragma unroll
        for (int i = 0; i < 4; i++) u[j][i] = kp[lane + (i << 5)];
    }

    cudaGridDependencySynchronize();

    for (int d = tid; d < DM_; d += 256) {
        float s = b2[d];
#pragma unroll
        for (int sp = 0; sp < 4; sp++) s += g_qpart[sp*NB_*DM_ + n*DM_ + d];
        qs[d] = s;
    }
    __syncthreads();

    float acc[4] = {};
#pragma unroll
    for (int i = 0; i < 4; i++) {
        const int d0 = (lane + (i << 5)) << 3;
        float4 q1 = *(const float4*)&qs[d0];
        float4 q2 = *(const float4*)&qs[d0 + 4];
        float4 v1 = *(const float4*)&vs[d0];
        float4 v2 = *(const float4*)&vs[d0 + 4];
#pragma unroll
        for (int j = 0; j < 4; j++) {
            const __half2* hp = (const __half2*)&u[j][i];
            float2 f0 = __half22float2(hp[0]);
            float2 f1 = __half22float2(hp[1]);
            float2 f2 = __half22float2(hp[2]);
            float2 f3 = __half22float2(hp[3]);
            float a = acc[j];
            a = fmaf(tanh_approx(f0.x + q1.x), v1.x, a);
            a = fmaf(tanh_approx(f0.y + q1.y), v1.y, a);
            a = fmaf(tanh_approx(f1.x + q1.z), v1.z, a);
            a = fmaf(tanh_approx(f1.y + q1.w), v1.w, a);
            a = fmaf(tanh_approx(f2.x + q2.x), v2.x, a);
            a = fmaf(tanh_approx(f2.y + q2.y), v2.y, a);
            a = fmaf(tanh_approx(f3.x + q2.z), v2.z, a);
            a = fmaf(tanh_approx(f3.y + q2.w), v2.w, a);
            acc[j] = a;
        }
    }
#pragma unroll
    for (int j = 0; j < 4; j++) {
#pragma unroll
        for (int off = 16; off; off >>= 1)
            acc[j] += __shfl_xor_sync(0xffffffffu, acc[j], off);
        if (lane == 0 && (r0 + j) < TENC_)
            g_scores[n*TENC_ + r0 + j] = acc[j] + bvv;
    }
    cudaTriggerProgrammaticLaunchCompletion();
}

// ---------------- softmax + context — half2/thread, 10-row unroll, PDL -------
// grid (2 dc, 4 tc, 32 n): thread owns 2 d-columns (half2), 10 independent
// 4B loads in flight.
__global__ __launch_bounds__(256) void context_part(void)
{
    __shared__ float ws[TENC_];
    __shared__ float red[256];
    const int n  = blockIdx.z;
    const int tc = blockIdx.y;
    const int dc = blockIdx.x;
    const int tid = threadIdx.x;

    cudaGridDependencySynchronize();

    float mx = -1e30f;
    for (int t = tid; t < TENC_; t += 256) {
        float s = g_scores[n*TENC_ + t];
        ws[t] = s;
        mx = fmaxf(mx, s);
    }
    red[tid] = mx; __syncthreads();
    for (int s = 128; s; s >>= 1) {
        if (tid < s) red[tid] = fmaxf(red[tid], red[tid+s]);
        __syncthreads();
    }
    mx = red[0];
    __syncthreads();
    float lsum = 0.f;
    for (int t = tid; t < TENC_; t += 256) {
        float e = __expf(ws[t] - mx);
        ws[t] = e;
        lsum += e;
    }
    red[tid] = lsum; __syncthreads();
    for (int s = 128; s; s >>= 1) {
        if (tid < s) red[tid] += red[tid+s];
        __syncthreads();
    }
    const float inv = 1.f / red[0];

    // context: thread handles d = dc*512 + tid*2 (+1); rows tt0..tt0+124
    const int tt0 = tc * 125;
    const __half2* xp = (const __half2*)(g_xh + (size_t)n * TENC_ * D_)
                        + dc*256 + tid;             // row stride 512 half2
    float ax[10], ay[10];
#pragma unroll
    for (int u = 0; u < 10; u++) { ax[u] = 0.f; ay[u] = 0.f; }
    for (int t = tt0; t < tt0 + 120; t += 10) {     // 125 = 12*10 + 5
#pragma unroll
        for (int u = 0; u < 10; u++) {
            float2 f = __half22float2(xp[(size_t)(t + u) * 512]);
            float wv = ws[t + u];
            ax[u] = fmaf(wv, f.x, ax[u]);
            ay[u] = fmaf(wv, f.y, ay[u]);
        }
    }
#pragma unroll
    for (int u = 0; u < 5; u++) {
        int t = tt0 + 120 + u;
        float2 f = __half22float2(xp[(size_t)t * 512]);
        float wv = ws[t];
        ax[u] = fmaf(wv, f.x, ax[u]);
        ay[u] = fmaf(wv, f.y, ay[u]);
    }
    float sx = (((ax[0]+ax[1]) + (ax[2]+ax[3])) + ((ax[4]+ax[5]) + (ax[6]+ax[7])))
             + (ax[8]+ax[9]);
    float sy = (((ay[0]+ay[1]) + (ay[2]+ay[3])) + ((ay[4]+ay[5]) + (ay[6]+ay[7])))
             + (ay[8]+ay[9]);
    float2 o; o.x = sx * inv; o.y = sy * inv;
    *(float2*)&g_ctxpart[((size_t)tc * NB_ + n) * D_ + dc*512 + tid*2] = o;
    cudaTriggerProgrammaticLaunchCompletion();
}

// ---------------- fused gx-GEMM + GRU gate — PDL ------------------------------
__global__ __launch_bounds__(256) void gxgate_kernel(
    const float* __restrict__ b_rec, int t)
{
    __shared__ float As[256][36];
    __shared__ int last_flag;
    const int ug = blockIdx.x;
    const int kz = blockIdx.y;
    const int kbase = kz * 256;
    const int tid = threadIdx.x;

    cudaGridDependencySynchronize();

#pragma unroll 4
    for (int i = 0; i < 32; i++) {
        float s = g_ctxpart[(size_t)i * 1024 + kbase + tid];
#pragma unroll
        for (int p = 1; p < 4; p++)
            s += g_ctxpart[(size_t)p * (NB_*D_) + (size_t)i * 1024 + kbase + tid];
        As[tid][i] = s;
    }
    __syncthreads();

    const int tx = tid & 31, ty = tid >> 5;
    const int unit = ug * 32 + tx;
    const uint4* bz = (const uint4*)(g_Wxt + (size_t)unit          * 1024 + kbase);
    const uint4* br = (const uint4*)(g_Wxt + (size_t)(1024 + unit) * 1024 + kbase);
    const uint4* bh = (const uint4*)(g_Wxt + (size_t)(2048 + unit) * 1024 + kbase);

    float az[4] = {}, ar[4] = {}, ah[4] = {};
#pragma unroll 2
    for (int kk = 0; kk < 256; kk += 8) {
        uint4 uz = bz[kk >> 3], ur = br[kk >> 3], uh = bh[kk >> 3];
        const __half2 *hz = (const __half2*)&uz, *hr = (const __half2*)&ur,
                      *hhp = (const __half2*)&uh;
        float wz[8], wr[8], wh[8];
#pragma unroll
        for (int p = 0; p < 4; p++) {
            float2 fz = __half22float2(hz[p]);  wz[2*p] = fz.x; wz[2*p+1] = fz.y;
            float2 fr = __half22float2(hr[p]);  wr[2*p] = fr.x; wr[2*p+1] = fr.y;
            float2 fh = __half22float2(hhp[p]); wh[2*p] = fh.x; wh[2*p+1] = fh.y;
        }
#pragma unroll
        for (int u8 = 0; u8 < 8; u8++) {
            float4 a = *(const float4*)&As[kk + u8][ty * 4];
#pragma unroll
            for (int i = 0; i < 4; i++) {
                float av = (&a.x)[i];
                az[i] = fmaf(wz[u8], av, az[i]);
                ar[i] = fmaf(wr[u8], av, ar[i]);
                ah[i] = fmaf(wh[u8], av, ah[i]);
            }
        }
    }

#pragma unroll
    for (int i = 0; i < 4; i++) {
        const int n = ty * 4 + i;
        g_gxp[((size_t)(kz*3 + 0) * NB_ + n) * DM_ + unit] = az[i];
        g_gxp[((size_t)(kz*3 + 1) * NB_ + n) * DM_ + unit] = ar[i];
        g_gxp[((size_t)(kz*3 + 2) * NB_ + n) * DM_ + unit] = ah[i];
    }
    __threadfence();
    __syncthreads();
    if (tid == 0)
        last_flag = (atomicAdd(&g_ugcnt[ug], 1) == 3);
    __syncthreads();

    if (last_flag) {
        __threadfence();
        const float brz = b_rec[unit];
        const float brr = b_rec[unit + 1024];
        const float brh = b_rec[unit + 2048];
#pragma unroll
        for (int i = 0; i < 4; i++) {
            const int n = ty * 4 + i;
            float xz = 0.f, xr = 0.f, xh = 0.f;
#pragma unroll
            for (int z = 0; z < 4; z++) {
                xz += g_gxp[((size_t)(z*3 + 0) * NB_ + n) * DM_ + unit];
                xr += g_gxp[((size_t)(z*3 + 1) * NB_ + n) * DM_ + unit];
                xh += g_gxp[((size_t)(z*3 + 2) * NB_ + n) * DM_ + unit];
            }
            const float* ge = g_gxemb + (size_t)(n*TDEC_ + t) * G3_;
            xz += ge[unit]; xr += ge[unit + 1024]; xh += ge[unit + 2048];

            float zg = 1.f / (1.f + __expf(-(xz + brz)));
            float rg = 1.f / (1.f + __expf(-(xr + brr)));
            float hg = tanhf(xh + rg * brh);
            float hv = (1.f - zg) * hg;

            g_h[n * DM_ + unit] = hv;
            g_H[(size_t)(n*TDEC_ + t) * DM_ + unit] = hv;
        }
        __syncthreads();
        if (tid == 0) g_ugcnt[ug] = 0;
    }
}

// ---------------- PDL launch helper ------------------------------------------
template <typename F, typename... Args>
static inline void launch_pdl(dim3 g, dim3 b, F f, Args... args)
{
    cudaLaunchAttribute attr;
    attr.id = cudaLaunchAttributeProgrammaticStreamSerialization;
    attr.val.programmaticStreamSerializationAllowed = 1;
    cudaLaunchConfig_t cfg = {};
    cfg.gridDim = g; cfg.blockDim = b;
    cfg.dynamicSmemBytes = 0;
    cfg.stream = 0;
    cfg.attrs = &attr; cfg.numAttrs = 1;
    cudaLaunchKernelEx(&cfg, f, args...);
}

// ---------------- launch -----------------------------------------------------
extern "C" void kernel_launch(void* const* d_in, const int* in_sizes, int n_in,
                              void* d_out, int out_size)
{
    (void)in_sizes; (void)n_in; (void)out_size;
    const float* x    = (const float*)d_in[0];
    const float* m    = (const float*)d_in[1];
    const int*   y    = (const int*)  d_in[2];
    const float* emb  = (const float*)d_in[3];
    const float* W1   = (const float*)d_in[4];
    const float* b1   = (const float*)d_in[5];
    const float* W2   = (const float*)d_in[6];
    const float* b2   = (const float*)d_in[7];
    const float* v    = (const float*)d_in[8];
    const float* bv   = (const float*)d_in[9];
    const float* Wx   = (const float*)d_in[10];
    // d_in[11] = Uh — provably unused (h_prev == 0)
    const float* b_in = (const float*)d_in[12];
    const float* b_rec= (const float*)d_in[13];
    const float* Wo   = (const float*)d_in[14];
    const float* bo   = (const float*)d_in[15];
    float* out = (float*)d_out;

    __half *keysh, *xh, *W2t, *Wxt;
    __nv_bfloat16 *Ah, *Al, *Bh, *Bl;
    float *yemb, *gxemb, *qpart, *h, *H;
    cudaGetSymbolAddress((void**)&keysh,  g_keysh);
    cudaGetSymbolAddress((void**)&xh,     g_xh);
    cudaGetSymbolAddress((void**)&W2t,    g_W2t);
    cudaGetSymbolAddress((void**)&Wxt,    g_Wxt);
    cudaGetSymbolAddress((void**)&yemb,   g_yemb);
    cudaGetSymbolAddress((void**)&gxemb,  g_gxemb);
    cudaGetSymbolAddress((void**)&qpart,  g_qpart);
    cudaGetSymbolAddress((void**)&h,      g_h);
    cudaGetSymbolAddress((void**)&H,      g_H);
    cudaGetSymbolAddress((void**)&Ah,     g_Ah);
    cudaGetSymbolAddress((void**)&Al,     g_Al);
    cudaGetSymbolAddress((void**)&Bh,     g_Bh);
    cudaGetSymbolAddress((void**)&Bl,     g_Bl);

    cudaFuncSetAttribute(hgemm_split<__half>,
        cudaFuncAttributeMaxDynamicSharedMemorySize, HG_SMEM_BYTES);
    cudaFuncSetAttribute(hgemm_split<float>,
        cudaFuncAttributeMaxDynamicSharedMemorySize, HG_SMEM_BYTES);

    // ---- step-invariant precompute ----
    gather_emb<<<(NB_*TDEC_*E_ + 255)/256, 256>>>(y, emb, yemb);

    split_bf16<<<(16000*1024/4 + 255)/256, 256>>>(x,  Ah, Al, 16000*1024/4);
    split_bf16<<<(1024*1024/4  + 255)/256, 256>>>(W1, Bh, Bl, 1024*1024/4);
    hgemm_split<__half><<<dim3(16000/128, 1024/128), 256, HG_SMEM_BYTES>>>(
        Ah, Al, Bh, Bl, b1, keysh, 16000, 1024, 1024);

    split_bf16<<<(3200*256/4 + 255)/256, 256>>>(yemb, Ah, Al, 3200*256/4);
    split_bf16<<<(256*3072/4 + 255)/256, 256>>>(Wx + (size_t)1024*G3_, Bh, Bl,
                                                256*3072/4);
    hgemm_split<float><<<dim3(3200/128, 3072/128), 256, HG_SMEM_BYTES>>>(
        Ah, Al, Bh, Bl, b_in, gxemb, 3200, 3072, 256);

    transpose_f16<<<dim3(1024/32, 1024/32), dim3(32,8)>>>(W2, W2t, 1024, 1024);
    transpose_f16<<<dim3(3072/32, 1024/32), dim3(32,8)>>>(Wx, Wxt, 1024, 3072);
    f32_to_f16<<<(NB_*TENC_*D_/4 + 255)/256, 256>>>(x, xh, NB_*TENC_*D_/4);
    cudaMemcpyAsync(h, m, (size_t)NB_*DM_*sizeof(float), cudaMemcpyDeviceToDevice);

    // ---- sequential decode loop (4 PDL kernels/step) ----
    for (int t = 0; t < TDEC_; t++) {
        launch_pdl(dim3(DM_/32, 4), dim3(256), gemm_skinny_h,
                   (const float*)h, (const __half*)W2t, qpart, (int)DM_);
        launch_pdl(dim3(16, NB_), dim3(256), score_kernel, b2, v, bv);
        launch_pdl(dim3(2, 4, NB_), dim3(256), context_part);
        launch_pdl(dim3(32, 4), dim3(256), gxgate_kernel, b_rec, t);
    }

    // ---- out = H @ Wo + bo via split-bf16 tensor cores ----
    split_bf16<<<(3200*1024/4 + 255)/256, 256>>>(H,  Ah, Al, 3200*1024/4);
    split_bf16<<<(1024*8000/4 + 255)/256, 256>>>(Wo, Bh, Bl, 1024*8000/4);
    hgemm_split<float><<<dim3(3200/128, (8000 + 127)/128), 256, HG_SMEM_BYTES>>>(
        Ah, Al, Bh, Bl, bo, out, 3200, 8000, 1024);
}